// round 1
// baseline (speedup 1.0000x reference)
#include <cuda_runtime.h>
#include <cuda_bf16.h>

// Problem constants
#define VD 128           // volume D
#define VH 128           // volume H
#define VW 128           // volume W
#define NP 4             // projections
#define RD 192           // res_d
#define RH 192           // res_h
#define NW 128           // ray steps (w)
#define NPIX (NP*RD*RH)  // 147456 output pixels (per batch)
#define BATCH 2
#define OH 256
#define OW 256

// Scratch for x_proj[b][p][rd][rh]  (2*4*192*192 floats = 1.125 MB)
__device__ float g_xproj[BATCH * NPIX];

__device__ __forceinline__ int clampi(int v, int lo, int hi) {
    return v < lo ? lo : (v > hi ? hi : v);
}

// One warp per (p, rd, rh) pixel. Lane l handles w = l, l+32, l+64, l+96.
__global__ __launch_bounds__(256, 8)
void proj_kernel(const float* __restrict__ x,
                 const float* __restrict__ grids,
                 const float* __restrict__ dx)
{
    const int warp_global = (blockIdx.x * blockDim.x + threadIdx.x) >> 5;
    const int lane = threadIdx.x & 31;
    if (warp_global >= NPIX) return;

    const float* __restrict__ g = grids + (size_t)warp_global * (NW * 3);
    const float* __restrict__ v0 = x;
    const float* __restrict__ v1 = x + (size_t)VD * VH * VW;

    float s0 = 0.0f;
    float s1 = 0.0f;

    #pragma unroll
    for (int step = 0; step < 4; ++step) {
        const int w = lane + step * 32;
        const float c0 = __ldg(&g[w * 3 + 0]);
        const float c1 = __ldg(&g[w * 3 + 1]);
        const float c2 = __ldg(&g[w * 3 + 2]);

        // coords -> voxel space. c0 -> W axis, c1 -> H axis, c2 -> D axis.
        const float ix = (c0 + 1.0f) * (0.5f * (VW - 1));
        const float iy = (c1 + 1.0f) * (0.5f * (VH - 1));
        const float iz = (c2 + 1.0f) * (0.5f * (VD - 1));

        const float x0f = floorf(ix);
        const float y0f = floorf(iy);
        const float z0f = floorf(iz);
        const float fx = ix - x0f;
        const float fy = iy - y0f;
        const float fz = iz - z0f;
        const int x0 = (int)x0f;
        const int y0 = (int)y0f;
        const int z0 = (int)z0f;

        // Per-dimension tap weights, zeroed when that tap is out of bounds.
        // Product of per-dim weights == reference's "valid" masking.
        float wx0 = (x0 >= 0     && x0 <= VW - 1) ? (1.0f - fx) : 0.0f;
        float wx1 = (x0 + 1 >= 0 && x0 + 1 <= VW - 1) ? fx : 0.0f;
        float wy0 = (y0 >= 0     && y0 <= VH - 1) ? (1.0f - fy) : 0.0f;
        float wy1 = (y0 + 1 >= 0 && y0 + 1 <= VH - 1) ? fy : 0.0f;
        float wz0 = (z0 >= 0     && z0 <= VD - 1) ? (1.0f - fz) : 0.0f;
        float wz1 = (z0 + 1 >= 0 && z0 + 1 <= VD - 1) ? fz : 0.0f;

        const int xc0 = clampi(x0, 0, VW - 1);
        const int xc1 = clampi(x0 + 1, 0, VW - 1);
        const int yc0 = clampi(y0, 0, VH - 1);
        const int yc1 = clampi(y0 + 1, 0, VH - 1);
        const int zc0 = clampi(z0, 0, VD - 1);
        const int zc1 = clampi(z0 + 1, 0, VD - 1);

        const int r00 = (zc0 * VH + yc0) * VW;
        const int r01 = (zc0 * VH + yc1) * VW;
        const int r10 = (zc1 * VH + yc0) * VW;
        const int r11 = (zc1 * VH + yc1) * VW;

        const float w00 = wz0 * wy0;
        const float w01 = wz0 * wy1;
        const float w10 = wz1 * wy0;
        const float w11 = wz1 * wy1;

        // batch 0
        {
            float a = __ldg(&v0[r00 + xc0]) * wx0 + __ldg(&v0[r00 + xc1]) * wx1;
            float b = __ldg(&v0[r01 + xc0]) * wx0 + __ldg(&v0[r01 + xc1]) * wx1;
            float c = __ldg(&v0[r10 + xc0]) * wx0 + __ldg(&v0[r10 + xc1]) * wx1;
            float d = __ldg(&v0[r11 + xc0]) * wx0 + __ldg(&v0[r11 + xc1]) * wx1;
            s0 += w00 * a + w01 * b + w10 * c + w11 * d;
        }
        // batch 1 (same indices/weights)
        {
            float a = __ldg(&v1[r00 + xc0]) * wx0 + __ldg(&v1[r00 + xc1]) * wx1;
            float b = __ldg(&v1[r01 + xc0]) * wx0 + __ldg(&v1[r01 + xc1]) * wx1;
            float c = __ldg(&v1[r10 + xc0]) * wx0 + __ldg(&v1[r10 + xc1]) * wx1;
            float d = __ldg(&v1[r11 + xc0]) * wx0 + __ldg(&v1[r11 + xc1]) * wx1;
            s1 += w00 * a + w01 * b + w10 * c + w11 * d;
        }
    }

    // Warp reduction over the 128 ray steps.
    #pragma unroll
    for (int off = 16; off > 0; off >>= 1) {
        s0 += __shfl_xor_sync(0xFFFFFFFFu, s0, off);
        s1 += __shfl_xor_sync(0xFFFFFFFFu, s1, off);
    }

    if (lane == 0) {
        const float d = __ldg(&dx[warp_global]);
        g_xproj[warp_global]        = s0 * d;
        g_xproj[NPIX + warp_global] = s1 * d;
    }
}

// Nearest resize (192,192) -> (256,256): hi = oh*3/4, wi = ow*3/4.
__global__ __launch_bounds__(256)
void resize_kernel(float* __restrict__ out)
{
    const int tid = blockIdx.x * blockDim.x + threadIdx.x;
    if (tid >= BATCH * NP * OH * OW) return;
    const int ow = tid & (OW - 1);
    const int oh = (tid >> 8) & (OH - 1);
    const int c  = tid >> 16;             // c = b*NP + p
    const int hi = (oh * 3) >> 2;         // == oh*192/256, max 191
    const int wi = (ow * 3) >> 2;
    out[tid] = g_xproj[(size_t)c * (RD * RH) + hi * RH + wi];
}

extern "C" void kernel_launch(void* const* d_in, const int* in_sizes, int n_in,
                              void* d_out, int out_size)
{
    const float* x     = (const float*)d_in[0];
    const float* grids = (const float*)d_in[1];
    const float* dx    = (const float*)d_in[2];
    float* out = (float*)d_out;

    // proj: one warp per pixel, 8 warps per block
    const int warps = NPIX;
    const int blocks = (warps * 32 + 255) / 256;   // 18432
    proj_kernel<<<blocks, 256>>>(x, grids, dx);

    const int total = BATCH * NP * OH * OW;        // 524288
    resize_kernel<<<(total + 255) / 256, 256>>>(out);
}

// round 2
// speedup vs baseline: 5.1703x; 5.1703x over previous
#include <cuda_runtime.h>
#include <cuda_bf16.h>

// Problem constants
#define VD 128           // volume D  (input axis d)
#define VH 128           // volume H  (input axis w = ray march)
#define VW 128           // volume W  (input axis h)
#define NP 4             // projections
#define RD 192           // res_d
#define RH 192           // res_h
#define NW 128           // ray steps (w)
#define NPIX (NP*RD*RH)  // 147456 pixels per batch
#define BATCH 2
#define OH 256
#define OW 256

// Scratch
__device__ float g_xproj[BATCH * NPIX];                 // x_proj[b][p][rd][rh]
__device__ float g_tabWt[NP * NW * RH];                 // c0 table, [p][w][rh] (transposed)
__device__ float g_tabD [NP * RD * NW];                 // c2 table, [p][rd][w]
__device__ float g_tabH [NW];                           // c1 table, [w]

__device__ __forceinline__ int clampi(int v, int lo, int hi) {
    return v < lo ? lo : (v > hi ? hi : v);
}

// ---------------------------------------------------------------------------
// Phase A: extract separable coordinate tables from the (redundant) grid.
//   c0 = grids[p][rd][rh][w][0] depends only on (p, rh, w)  -> read at rd=0
//   c1 = grids[p][rd][rh][w][1] depends only on (w)         -> read at (0,0,0)
//   c2 = grids[p][rd][rh][w][2] depends only on (p, rd, w)  -> read at rh=0
// ---------------------------------------------------------------------------
__global__ __launch_bounds__(256)
void extract_kernel(const float* __restrict__ grids)
{
    const int tid = blockIdx.x * blockDim.x + threadIdx.x;
    const int NA = NP * NW * RH;   // tabWt entries
    const int NB = NP * RD * NW;   // tabD entries
    if (tid < NA) {
        // tid = (p*NW + w)*RH + rh
        int rh = tid % RH;
        int pw = tid / RH;
        int w  = pw % NW;
        int p  = pw / NW;
        g_tabWt[tid] = grids[(((size_t)(p * RD + 0) * RH + rh) * NW + w) * 3 + 0];
    } else if (tid < NA + NB) {
        int t = tid - NA;          // t = (p*RD + rd)*NW + w
        int w   = t % NW;
        int prd = t / NW;
        g_tabD[t] = grids[(((size_t)prd * RH + 0) * NW + w) * 3 + 2];
    } else if (tid < NA + NB + NW) {
        int w = tid - NA - NB;
        g_tabH[w] = grids[(size_t)w * 3 + 1];
    }
}

// ---------------------------------------------------------------------------
// Phase B: one block per (p, rd); 192 threads = the rh line.
// Lanes march along the volume's stride-1 W axis -> gathers hit 1-2 lines.
// y/z side (uniform over rh) precomputed into smem once per block.
// ---------------------------------------------------------------------------
__global__ __launch_bounds__(192)
void proj2_kernel(const float* __restrict__ x,
                  const float* __restrict__ dx)
{
    const int blk = blockIdx.x;           // = p*RD + rd
    const int p   = blk / RD;
    const int rh  = threadIdx.x;

    __shared__ int   s_row[4][NW];        // row base offsets (z,y combos)
    __shared__ float s_wzy[4][NW];        // combined wz*wy weights

    if (threadIdx.x < NW) {
        const int w = threadIdx.x;
        const float c1 = g_tabH[w];
        const float c2 = g_tabD[blk * NW + w];
        const float iy = (c1 + 1.0f) * (0.5f * (VH - 1));
        const float iz = (c2 + 1.0f) * (0.5f * (VD - 1));
        const float y0f = floorf(iy);
        const float z0f = floorf(iz);
        const float fy = iy - y0f;
        const float fz = iz - z0f;
        const int y0 = (int)y0f;
        const int z0 = (int)z0f;

        float wy0 = (y0 >= 0     && y0     <= VH - 1) ? (1.0f - fy) : 0.0f;
        float wy1 = (y0 + 1 >= 0 && y0 + 1 <= VH - 1) ? fy : 0.0f;
        float wz0 = (z0 >= 0     && z0     <= VD - 1) ? (1.0f - fz) : 0.0f;
        float wz1 = (z0 + 1 >= 0 && z0 + 1 <= VD - 1) ? fz : 0.0f;

        const int yc0 = clampi(y0,     0, VH - 1);
        const int yc1 = clampi(y0 + 1, 0, VH - 1);
        const int zc0 = clampi(z0,     0, VD - 1);
        const int zc1 = clampi(z0 + 1, 0, VD - 1);

        s_row[0][w] = (zc0 * VH + yc0) * VW;  s_wzy[0][w] = wz0 * wy0;
        s_row[1][w] = (zc0 * VH + yc1) * VW;  s_wzy[1][w] = wz0 * wy1;
        s_row[2][w] = (zc1 * VH + yc0) * VW;  s_wzy[2][w] = wz1 * wy0;
        s_row[3][w] = (zc1 * VH + yc1) * VW;  s_wzy[3][w] = wz1 * wy1;
    }
    __syncthreads();

    const float* __restrict__ v0 = x;
    const float* __restrict__ v1 = x + (size_t)VD * VH * VW;
    const float* __restrict__ tw = g_tabWt + (size_t)p * NW * RH + rh;

    float s0 = 0.0f;
    float s1 = 0.0f;

    #pragma unroll 2
    for (int w = 0; w < NW; ++w) {
        const float c0 = tw[(size_t)w * RH];                 // coalesced across lanes
        const float ix = (c0 + 1.0f) * (0.5f * (VW - 1));
        const float x0f = floorf(ix);
        const float fx = ix - x0f;
        const int x0 = (int)x0f;

        float wx0 = (x0 >= 0     && x0     <= VW - 1) ? (1.0f - fx) : 0.0f;
        float wx1 = (x0 + 1 >= 0 && x0 + 1 <= VW - 1) ? fx : 0.0f;
        const int xc0 = clampi(x0,     0, VW - 1);
        const int xc1 = clampi(x0 + 1, 0, VW - 1);

        float acc0 = 0.0f, acc1 = 0.0f;
        #pragma unroll
        for (int k = 0; k < 4; ++k) {
            const int   r  = s_row[k][w];                    // smem broadcast
            const float wk = s_wzy[k][w];
            const float a0 = __ldg(&v0[r + xc0]);
            const float b0 = __ldg(&v0[r + xc1]);
            const float a1 = __ldg(&v1[r + xc0]);
            const float b1 = __ldg(&v1[r + xc1]);
            acc0 += wk * (a0 * wx0 + b0 * wx1);
            acc1 += wk * (a1 * wx0 + b1 * wx1);
        }
        s0 += acc0;
        s1 += acc1;
    }

    const int pix = blk * RH + rh;
    const float d = __ldg(&dx[pix]);
    g_xproj[pix]        = s0 * d;
    g_xproj[NPIX + pix] = s1 * d;
}

// Nearest resize (192,192) -> (256,256): hi = oh*3/4, wi = ow*3/4.
__global__ __launch_bounds__(256)
void resize_kernel(float* __restrict__ out)
{
    const int tid = blockIdx.x * blockDim.x + threadIdx.x;
    if (tid >= BATCH * NP * OH * OW) return;
    const int ow = tid & (OW - 1);
    const int oh = (tid >> 8) & (OH - 1);
    const int c  = tid >> 16;             // c = b*NP + p
    const int hi = (oh * 3) >> 2;
    const int wi = (ow * 3) >> 2;
    out[tid] = g_xproj[(size_t)c * (RD * RH) + hi * RH + wi];
}

extern "C" void kernel_launch(void* const* d_in, const int* in_sizes, int n_in,
                              void* d_out, int out_size)
{
    const float* x     = (const float*)d_in[0];
    const float* grids = (const float*)d_in[1];
    const float* dx    = (const float*)d_in[2];
    float* out = (float*)d_out;

    // Phase A: extract separable tables
    const int n_ext = NP * NW * RH + NP * RD * NW + NW;
    extract_kernel<<<(n_ext + 255) / 256, 256>>>(grids);

    // Phase B: projection, one block per (p, rd)
    proj2_kernel<<<NP * RD, 192>>>(x, dx);

    // Resize to output
    const int total = BATCH * NP * OH * OW;
    resize_kernel<<<(total + 255) / 256, 256>>>(out);
}

// round 3
// speedup vs baseline: 6.7029x; 1.2964x over previous
#include <cuda_runtime.h>
#include <cuda_bf16.h>

// Problem constants
#define VD 128
#define VH 128
#define VW 128
#define VOL (VD*VH*VW)     // 2097152
#define NP 4
#define RD 192
#define RH 192
#define NW 128
#define NPIX (NP*RD*RH)    // 147456 per batch
#define BATCH 2
#define OH 256
#define OW 256
#define WHALF 64           // w-steps per half-block

// Scratch
__device__ float2 g_vol2[VOL];                   // {batch0, batch1} interleaved (16 MB)
__device__ float  g_xproj[2][BATCH * NPIX];      // partial sums per w-half
__device__ float  g_tabWt[NP * NW * RH];         // c0 table, [p][w][rh]
__device__ float  g_tabD [NP * RD * NW];         // c2 table, [p][rd][w]
__device__ float  g_tabH [NW];                   // c1 table, [w]

__device__ __forceinline__ int clampi(int v, int lo, int hi) {
    return v < lo ? lo : (v > hi ? hi : v);
}

// ---------------------------------------------------------------------------
// Pack both batch volumes into interleaved float2.
// ---------------------------------------------------------------------------
__global__ __launch_bounds__(256)
void pack_kernel(const float* __restrict__ x)
{
    const int i = blockIdx.x * blockDim.x + threadIdx.x;
    if (i < VOL)
        g_vol2[i] = make_float2(__ldg(&x[i]), __ldg(&x[i + VOL]));
}

// ---------------------------------------------------------------------------
// Extract separable coordinate tables (grid is rank-deficient; see R1 notes).
// ---------------------------------------------------------------------------
__global__ __launch_bounds__(256)
void extract_kernel(const float* __restrict__ grids)
{
    const int tid = blockIdx.x * blockDim.x + threadIdx.x;
    const int NA = NP * NW * RH;
    const int NB = NP * RD * NW;
    if (tid < NA) {
        int rh = tid % RH;
        int pw = tid / RH;
        int w  = pw % NW;
        int p  = pw / NW;
        g_tabWt[tid] = grids[(((size_t)(p * RD + 0) * RH + rh) * NW + w) * 3 + 0];
    } else if (tid < NA + NB) {
        int t = tid - NA;
        int w   = t % NW;
        int prd = t / NW;
        g_tabD[t] = grids[(((size_t)prd * RH + 0) * NW + w) * 3 + 2];
    } else if (tid < NA + NB + NW) {
        int w = tid - NA - NB;
        g_tabH[w] = grids[(size_t)w * 3 + 1];
    }
}

// ---------------------------------------------------------------------------
// Projection: block = (p*RD+rd, half); 192 threads = rh line; 64 w-steps.
// Gathers are LDG.64 fetching both batches at once.
// ---------------------------------------------------------------------------
__global__ __launch_bounds__(192)
void proj3_kernel(const float* __restrict__ dx)
{
    const int bid  = blockIdx.x;       // 0..1535
    const int half = bid & 1;
    const int blk  = bid >> 1;         // p*RD + rd
    const int p    = blk / RD;
    const int rh   = threadIdx.x;
    const int W0   = half * WHALF;

    __shared__ int2 s_rw[4][WHALF];    // {row base, wz*wy bits}

    if (threadIdx.x < WHALF) {
        const int w = W0 + threadIdx.x;
        const float c1 = g_tabH[w];
        const float c2 = g_tabD[blk * NW + w];
        const float iy = (c1 + 1.0f) * (0.5f * (VH - 1));
        const float iz = (c2 + 1.0f) * (0.5f * (VD - 1));
        const float y0f = floorf(iy);
        const float z0f = floorf(iz);
        const float fy = iy - y0f;
        const float fz = iz - z0f;
        const int y0 = (int)y0f;
        const int z0 = (int)z0f;

        float wy0 = (y0 >= 0     && y0     <= VH - 1) ? (1.0f - fy) : 0.0f;
        float wy1 = (y0 + 1 >= 0 && y0 + 1 <= VH - 1) ? fy : 0.0f;
        float wz0 = (z0 >= 0     && z0     <= VD - 1) ? (1.0f - fz) : 0.0f;
        float wz1 = (z0 + 1 >= 0 && z0 + 1 <= VD - 1) ? fz : 0.0f;

        const int yc0 = clampi(y0,     0, VH - 1);
        const int yc1 = clampi(y0 + 1, 0, VH - 1);
        const int zc0 = clampi(z0,     0, VD - 1);
        const int zc1 = clampi(z0 + 1, 0, VD - 1);

        s_rw[0][threadIdx.x] = make_int2((zc0 * VH + yc0) * VW, __float_as_int(wz0 * wy0));
        s_rw[1][threadIdx.x] = make_int2((zc0 * VH + yc1) * VW, __float_as_int(wz0 * wy1));
        s_rw[2][threadIdx.x] = make_int2((zc1 * VH + yc0) * VW, __float_as_int(wz1 * wy0));
        s_rw[3][threadIdx.x] = make_int2((zc1 * VH + yc1) * VW, __float_as_int(wz1 * wy1));
    }
    __syncthreads();

    const float* __restrict__ tw = g_tabWt + (size_t)p * NW * RH + rh;

    float s0 = 0.0f;
    float s1 = 0.0f;

    #pragma unroll 2
    for (int i = 0; i < WHALF; ++i) {
        const int w = W0 + i;
        const float c0 = __ldg(&tw[(size_t)w * RH]);         // coalesced
        const float ix = (c0 + 1.0f) * (0.5f * (VW - 1));
        const float x0f = floorf(ix);
        const float fx = ix - x0f;
        const int x0 = (int)x0f;

        float wx0 = (x0 >= 0     && x0     <= VW - 1) ? (1.0f - fx) : 0.0f;
        float wx1 = (x0 + 1 >= 0 && x0 + 1 <= VW - 1) ? fx : 0.0f;
        const int xc0 = clampi(x0,     0, VW - 1);
        const int xc1 = clampi(x0 + 1, 0, VW - 1);

        float acc0 = 0.0f, acc1 = 0.0f;
        #pragma unroll
        for (int k = 0; k < 4; ++k) {
            const int2  rw = s_rw[k][i];                     // LDS.64 broadcast
            const float wk = __int_as_float(rw.y);
            const float2 a = __ldg(&g_vol2[rw.x + xc0]);     // both batches
            const float2 b = __ldg(&g_vol2[rw.x + xc1]);
            acc0 += wk * (a.x * wx0 + b.x * wx1);
            acc1 += wk * (a.y * wx0 + b.y * wx1);
        }
        s0 += acc0;
        s1 += acc1;
    }

    const int pix = blk * RH + rh;
    const float d = __ldg(&dx[pix]);
    g_xproj[half][pix]        = s0 * d;
    g_xproj[half][NPIX + pix] = s1 * d;
}

// ---------------------------------------------------------------------------
// Nearest resize (192,192)->(256,256), summing the two w-half partials.
// ---------------------------------------------------------------------------
__global__ __launch_bounds__(256)
void resize_kernel(float* __restrict__ out)
{
    const int tid = blockIdx.x * blockDim.x + threadIdx.x;
    if (tid >= BATCH * NP * OH * OW) return;
    const int ow = tid & (OW - 1);
    const int oh = (tid >> 8) & (OH - 1);
    const int c  = tid >> 16;             // c = b*NP + p
    const int hi = (oh * 3) >> 2;
    const int wi = (ow * 3) >> 2;
    const size_t idx = (size_t)c * (RD * RH) + hi * RH + wi;
    out[tid] = g_xproj[0][idx] + g_xproj[1][idx];
}

extern "C" void kernel_launch(void* const* d_in, const int* in_sizes, int n_in,
                              void* d_out, int out_size)
{
    const float* x     = (const float*)d_in[0];
    const float* grids = (const float*)d_in[1];
    const float* dx    = (const float*)d_in[2];
    float* out = (float*)d_out;

    pack_kernel<<<(VOL + 255) / 256, 256>>>(x);

    const int n_ext = NP * NW * RH + NP * RD * NW + NW;
    extract_kernel<<<(n_ext + 255) / 256, 256>>>(grids);

    proj3_kernel<<<NP * RD * 2, 192>>>(dx);

    const int total = BATCH * NP * OH * OW;
    resize_kernel<<<(total + 255) / 256, 256>>>(out);
}

// round 4
// speedup vs baseline: 7.8111x; 1.1653x over previous
#include <cuda_runtime.h>
#include <cuda_bf16.h>

// Problem constants
#define VD 128
#define VH 128
#define VW 128
#define VOL (VD*VH*VW)     // 2097152
#define NP 4
#define RD 192
#define RH 192
#define NW 128
#define NPIX (NP*RD*RH)    // 147456 per batch
#define BATCH 2
#define OH 256
#define OW 256
#define NQ 4               // ray quarters
#define WQ (NW/NQ)         // 32 w-steps per block

// Scratch
__device__ float4 g_vol4[VOL];                   // {b0[i],b0[i+1],b1[i],b1[i+1]} (32 MB)
__device__ float4 g_xprojP[NPIX * BATCH];        // [pix][b] -> 4 quarter-partials
__device__ float  g_tabWt[NP * NW * RH];         // c0 table, [p][w][rh]
__device__ float  g_tabD [NP * RD * NW];         // c2 table, [p][rd][w]
__device__ float  g_tabH [NW];                   // c1 table, [w]

__device__ __forceinline__ int clampi(int v, int lo, int hi) {
    return v < lo ? lo : (v > hi ? hi : v);
}

// ---------------------------------------------------------------------------
// Fused: pair-pack both batch volumes (blocks 0..8191) + table extraction
// (blocks 8192..). Extract's latency hides under pack's streaming.
// ---------------------------------------------------------------------------
#define PACK_BLOCKS (VOL/256)      // 8192
__global__ __launch_bounds__(256)
void prep_kernel(const float* __restrict__ x, const float* __restrict__ grids)
{
    if (blockIdx.x < PACK_BLOCKS) {
        const int i   = blockIdx.x * 256 + threadIdx.x;
        const int ip1 = (i + 1 < VOL) ? i + 1 : i;   // clamp; .y/.w unused at row end
        g_vol4[i] = make_float4(__ldg(&x[i]),       __ldg(&x[ip1]),
                                __ldg(&x[i + VOL]), __ldg(&x[ip1 + VOL]));
        return;
    }
    const int tid = (blockIdx.x - PACK_BLOCKS) * 256 + threadIdx.x;
    const int NA = NP * NW * RH;   // 98304
    const int NB = NP * RD * NW;   // 98304
    if (tid < NA) {
        int rh = tid % RH;
        int pw = tid / RH;
        int w  = pw % NW;
        int p  = pw / NW;
        g_tabWt[tid] = __ldg(&grids[(((size_t)(p * RD + 0) * RH + rh) * NW + w) * 3 + 0]);
    } else if (tid < NA + NB) {
        int t = tid - NA;
        g_tabD[t] = __ldg(&grids[(((size_t)(t / NW) * RH + 0) * NW + (t % NW)) * 3 + 2]);
    } else if (tid < NA + NB + NW) {
        int w = tid - NA - NB;
        g_tabH[w] = __ldg(&grids[(size_t)w * 3 + 1]);
    }
}

// ---------------------------------------------------------------------------
// Projection: block = (p*RD+rd)*NQ + q; 192 threads = rh line; WQ w-steps.
// One LDG.128 per (z,y) row fetches both x-taps for both batches.
// ---------------------------------------------------------------------------
__global__ __launch_bounds__(192)
void proj4_kernel(const float* __restrict__ dx)
{
    const int bid = blockIdx.x;
    const int q   = bid & (NQ - 1);
    const int blk = bid >> 2;          // p*RD + rd
    const int p   = blk / RD;
    const int rh  = threadIdx.x;
    const int W0  = q * WQ;

    __shared__ int2 s_rw[4][WQ];       // {row base, wz*wy bits}

    if (threadIdx.x < WQ) {
        const int w = W0 + threadIdx.x;
        const float c1 = g_tabH[w];
        const float c2 = g_tabD[blk * NW + w];
        const float iy = (c1 + 1.0f) * (0.5f * (VH - 1));
        const float iz = (c2 + 1.0f) * (0.5f * (VD - 1));
        const float y0f = floorf(iy);
        const float z0f = floorf(iz);
        const float fy = iy - y0f;
        const float fz = iz - z0f;
        const int y0 = (int)y0f;
        const int z0 = (int)z0f;

        float wy0 = (y0 >= 0     && y0     <= VH - 1) ? (1.0f - fy) : 0.0f;
        float wy1 = (y0 + 1 >= 0 && y0 + 1 <= VH - 1) ? fy : 0.0f;
        float wz0 = (z0 >= 0     && z0     <= VD - 1) ? (1.0f - fz) : 0.0f;
        float wz1 = (z0 + 1 >= 0 && z0 + 1 <= VD - 1) ? fz : 0.0f;

        const int yc0 = clampi(y0,     0, VH - 1);
        const int yc1 = clampi(y0 + 1, 0, VH - 1);
        const int zc0 = clampi(z0,     0, VD - 1);
        const int zc1 = clampi(z0 + 1, 0, VD - 1);

        s_rw[0][threadIdx.x] = make_int2((zc0 * VH + yc0) * VW, __float_as_int(wz0 * wy0));
        s_rw[1][threadIdx.x] = make_int2((zc0 * VH + yc1) * VW, __float_as_int(wz0 * wy1));
        s_rw[2][threadIdx.x] = make_int2((zc1 * VH + yc0) * VW, __float_as_int(wz1 * wy0));
        s_rw[3][threadIdx.x] = make_int2((zc1 * VH + yc1) * VW, __float_as_int(wz1 * wy1));
    }
    __syncthreads();

    const float* __restrict__ tw = g_tabWt + (size_t)p * NW * RH + rh;

    float s0 = 0.0f;
    float s1 = 0.0f;

    #pragma unroll 4
    for (int i = 0; i < WQ; ++i) {
        const int w = W0 + i;
        const float c0 = __ldg(&tw[(size_t)w * RH]);         // coalesced
        const float ix = (c0 + 1.0f) * (0.5f * (VW - 1));
        const float x0f = floorf(ix);
        const float fx = ix - x0f;
        const int x0 = (int)x0f;

        // Tap weights with edge remap onto the pair {v[e], v[e+1]}, e = clamp(x0,0,126).
        float wx0 = (x0 >= 0     && x0     <= VW - 1) ? (1.0f - fx) : 0.0f;
        float wx1 = (x0 + 1 >= 0 && x0 + 1 <= VW - 1) ? fx : 0.0f;
        float w0, w1;
        if (x0 < 0)            { w0 = wx1; w1 = 0.0f; }   // x0==-1: tap at v[0] = pair.x
        else if (x0 > VW - 2)  { w0 = 0.0f; w1 = wx0; }   // x0==127: tap at v[127] = pair.y
        else                   { w0 = wx0; w1 = wx1; }
        const int e = clampi(x0, 0, VW - 2);

        float acc0 = 0.0f, acc1 = 0.0f;
        #pragma unroll
        for (int k = 0; k < 4; ++k) {
            const int2   rw = s_rw[k][i];                  // LDS.64 broadcast
            const float  wk = __int_as_float(rw.y);
            const float4 v  = __ldg(&g_vol4[rw.x + e]);    // both taps, both batches
            acc0 += wk * (v.x * w0 + v.y * w1);
            acc1 += wk * (v.z * w0 + v.w * w1);
        }
        s0 += acc0;
        s1 += acc1;
    }

    const int pix = blk * RH + rh;
    const float d = __ldg(&dx[pix]);
    // One float per quarter; vec4 layout so resize reads a single LDG.128.
    ((float*)&g_xprojP[(size_t)pix * BATCH + 0])[q] = s0 * d;
    ((float*)&g_xprojP[(size_t)pix * BATCH + 1])[q] = s1 * d;
}

// ---------------------------------------------------------------------------
// Nearest resize (192,192)->(256,256), summing the 4 quarter partials.
// ---------------------------------------------------------------------------
__global__ __launch_bounds__(256)
void resize_kernel(float* __restrict__ out)
{
    const int tid = blockIdx.x * blockDim.x + threadIdx.x;
    if (tid >= BATCH * NP * OH * OW) return;
    const int ow = tid & (OW - 1);
    const int oh = (tid >> 8) & (OH - 1);
    const int c  = tid >> 16;             // c = b*NP + p
    const int b  = c >> 2;
    const int p  = c & 3;
    const int hi = (oh * 3) >> 2;
    const int wi = (ow * 3) >> 2;
    const size_t pix = (size_t)(p * RD + hi) * RH + wi;
    const float4 v = __ldg(&g_xprojP[pix * BATCH + b]);
    out[tid] = (v.x + v.y) + (v.z + v.w);
}

extern "C" void kernel_launch(void* const* d_in, const int* in_sizes, int n_in,
                              void* d_out, int out_size)
{
    const float* x     = (const float*)d_in[0];
    const float* grids = (const float*)d_in[1];
    const float* dx    = (const float*)d_in[2];
    float* out = (float*)d_out;

    const int n_ext = NP * NW * RH + NP * RD * NW + NW;            // 196736
    const int prep_blocks = PACK_BLOCKS + (n_ext + 255) / 256;     // 8192 + 769
    prep_kernel<<<prep_blocks, 256>>>(x, grids);

    proj4_kernel<<<NP * RD * NQ, 192>>>(dx);

    const int total = BATCH * NP * OH * OW;
    resize_kernel<<<(total + 255) / 256, 256>>>(out);
}